// round 2
// baseline (speedup 1.0000x reference)
#include <cuda_runtime.h>
#include <math.h>

#define NTOK 8192
#define DIM  768
#define FDIM 3072
#define NEXP 8

// ---------------- device-global scratch (no allocs allowed) ----------------
__device__ int   g_counts[NEXP];
__device__ int   g_counts2[NEXP];
__device__ int   g_offsets[NEXP + 1];
__device__ int   g_te[2 * NTOK];
__device__ float g_tw[2 * NTOK];
__device__ int   g_perm[2 * NTOK];
__device__ float g_permw[2 * NTOK];
__device__ float g_h[(size_t)2 * NTOK * FDIM];   // routed hidden, per slot (201 MB)
__device__ float g_hs[(size_t)NTOK * FDIM];      // shared hidden (100 MB)

// ---------------- small kernels ----------------
__global__ void zero_kernel() {
    int t = threadIdx.x;
    if (t < NEXP) { g_counts[t] = 0; g_counts2[t] = 0; }
}

// one warp per token: 8 expert logits, top-2, renormalized softmax weights
__global__ void gate_kernel(const float* __restrict__ x,
                            const float* __restrict__ gw) {
    int gid  = blockIdx.x * blockDim.x + threadIdx.x;
    int tok  = gid >> 5;
    int lane = gid & 31;
    if (tok >= NTOK) return;

    const float* xr = x + (size_t)tok * DIM;
    float xv[24];
#pragma unroll
    for (int i = 0; i < 24; i++) xv[i] = xr[lane + 32 * i];

    float logit[NEXP];
#pragma unroll
    for (int e = 0; e < NEXP; e++) {
        const float* w = gw + e * DIM;
        float s = 0.f;
#pragma unroll
        for (int i = 0; i < 24; i++) s = fmaf(xv[i], w[lane + 32 * i], s);
#pragma unroll
        for (int o = 16; o > 0; o >>= 1) s += __shfl_down_sync(0xffffffffu, s, o);
        logit[e] = s;
    }
    if (lane == 0) {
        int i1 = 0;
#pragma unroll
        for (int e = 1; e < NEXP; e++) if (logit[e] > logit[i1]) i1 = e;
        int i2 = (i1 == 0) ? 1 : 0;
#pragma unroll
        for (int e = 0; e < NEXP; e++) {
            if (e == i1 || e == i2) continue;
            if (logit[e] > logit[i2]) i2 = e;
        }
        float e2    = expf(logit[i2] - logit[i1]);
        float denom = 1.f + e2;
        g_te[2 * tok]     = i1;
        g_te[2 * tok + 1] = i2;
        g_tw[2 * tok]     = 1.f / denom;
        g_tw[2 * tok + 1] = e2 / denom;
        atomicAdd(&g_counts[i1], 1);
        atomicAdd(&g_counts[i2], 1);
    }
}

__global__ void offsets_kernel() {
    int s = 0;
    g_offsets[0] = 0;
#pragma unroll
    for (int e = 0; e < NEXP; e++) { s += g_counts[e]; g_offsets[e + 1] = s; }
}

__global__ void scatter_kernel() {
    int t = blockIdx.x * blockDim.x + threadIdx.x;
    if (t >= 2 * NTOK) return;
    int e   = g_te[t];
    int pos = g_offsets[e] + atomicAdd(&g_counts2[e], 1);
    g_perm[pos]  = t >> 1;     // token id
    g_permw[pos] = g_tw[t];    // renormalized gate weight
}

// ---------------- GEMM ----------------
__device__ __forceinline__ float gelu_f(float v) {
    return 0.5f * v * (1.f + erff(v * 0.70710678118654752f));
}

// MODE 0: shared fc1  (A = x,        C = g_hs, gelu)
// MODE 1: shared fc2  (A = g_hs,     C = out, store)
// MODE 2: routed fc1  (A = x gather, C = g_h,  gelu)     [blockIdx.z = expert]
// MODE 3: routed fc2  (A = g_h,      C = out, atomicAdd weighted)
template <int MODE, int KDIM, int NDIM>
__global__ __launch_bounds__(256)
void gemm_kernel(const float* __restrict__ Aext,
                 const float* __restrict__ B,
                 const float* __restrict__ bias,
                 float* __restrict__ Cext) {
    constexpr int BM = 128, BN = 64, BK = 16, TM = 8, TN = 4;
    __shared__ float As[BK][BM];
    __shared__ float Bs[BK][BN];

    const int tid = threadIdx.x;
    const int e = (MODE >= 2) ? (int)blockIdx.z : 0;
    int seg_start = 0, seg_len = NTOK;
    if (MODE >= 2) {
        seg_start = g_offsets[e];
        seg_len   = g_offsets[e + 1] - seg_start;
    }
    const int row0 = blockIdx.x * BM;
    if (row0 >= seg_len) return;
    const int col0 = blockIdx.y * BN;

    // ---- per-thread load assignments ----
    const int lm = tid >> 1;   // A row within tile (0..127)
    const int lc = tid & 1;    // A chunk (0/1; also +2)
    const int ln = tid >> 2;   // B row within tile (0..63)
    const int lcb = tid & 3;   // B chunk

    const float* arow;
    bool avalid = true;
    {
        int r = row0 + lm;
        if (MODE == 0) {
            arow = Aext + (size_t)r * KDIM;
        } else if (MODE == 1) {
            arow = g_hs + (size_t)r * KDIM;
        } else if (MODE == 2) {
            avalid = (r < seg_len);
            arow = Aext + (size_t)(avalid ? g_perm[seg_start + r] : 0) * KDIM;
        } else {
            avalid = (r < seg_len);
            arow = g_h + (size_t)(seg_start + (avalid ? r : 0)) * KDIM;
        }
    }
    const float* brow = B + ((size_t)e * NDIM + (col0 + ln)) * KDIM;

    float acc[TM][TN];
#pragma unroll
    for (int i = 0; i < TM; i++)
#pragma unroll
        for (int j = 0; j < TN; j++) acc[i][j] = 0.f;

    const int ty = tid >> 4;   // 0..15
    const int tx = tid & 15;   // 0..15

    for (int k0 = 0; k0 < KDIM; k0 += BK) {
        float4 a0, a1, bv;
        if (avalid) {
            a0 = *reinterpret_cast<const float4*>(arow + k0 + 4 * lc);
            a1 = *reinterpret_cast<const float4*>(arow + k0 + 4 * lc + 8);
        } else {
            a0 = make_float4(0.f, 0.f, 0.f, 0.f);
            a1 = a0;
        }
        bv = *reinterpret_cast<const float4*>(brow + k0 + 4 * lcb);

        __syncthreads();
        As[4 * lc + 0][lm] = a0.x;
        As[4 * lc + 1][lm] = a0.y;
        As[4 * lc + 2][lm] = a0.z;
        As[4 * lc + 3][lm] = a0.w;
        As[4 * lc + 8][lm] = a1.x;
        As[4 * lc + 9][lm] = a1.y;
        As[4 * lc + 10][lm] = a1.z;
        As[4 * lc + 11][lm] = a1.w;
        Bs[4 * lcb + 0][ln] = bv.x;
        Bs[4 * lcb + 1][ln] = bv.y;
        Bs[4 * lcb + 2][ln] = bv.z;
        Bs[4 * lcb + 3][ln] = bv.w;
        __syncthreads();

#pragma unroll
        for (int k = 0; k < BK; k++) {
            float a[TM], b[TN];
#pragma unroll
            for (int i = 0; i < TM; i++) a[i] = As[k][ty * TM + i];
#pragma unroll
            for (int j = 0; j < TN; j++) b[j] = Bs[k][tx * TN + j];
#pragma unroll
            for (int i = 0; i < TM; i++)
#pragma unroll
                for (int j = 0; j < TN; j++)
                    acc[i][j] = fmaf(a[i], b[j], acc[i][j]);
        }
    }

    // ---- epilogue ----
    const int rbase = row0 + ty * TM;
    const int cbase = col0 + tx * TN;
    const float* bp = bias + (size_t)e * NDIM;
#pragma unroll
    for (int i = 0; i < TM; i++) {
        int r = rbase + i;
        if (MODE >= 2 && r >= seg_len) continue;
#pragma unroll
        for (int j = 0; j < TN; j++) {
            int c = cbase + j;
            float v = acc[i][j] + bp[c];
            if (MODE == 0) {
                g_hs[(size_t)r * NDIM + c] = gelu_f(v);
            } else if (MODE == 1) {
                Cext[(size_t)r * NDIM + c] = v;
            } else if (MODE == 2) {
                g_h[(size_t)(seg_start + r) * NDIM + c] = gelu_f(v);
            } else {
                int tok = g_perm[seg_start + r];
                atomicAdd(&Cext[(size_t)tok * NDIM + c],
                          g_permw[seg_start + r] * v);
            }
        }
    }
}

// ---------------- launch ----------------
extern "C" void kernel_launch(void* const* d_in, const int* in_sizes, int n_in,
                              void* d_out, int out_size) {
    const float* x   = (const float*)d_in[0];
    const float* gw  = (const float*)d_in[1];
    const float* w1  = (const float*)d_in[2];
    const float* b1  = (const float*)d_in[3];
    const float* w2  = (const float*)d_in[4];
    const float* b2  = (const float*)d_in[5];
    const float* ws1 = (const float*)d_in[6];
    const float* bs1 = (const float*)d_in[7];
    const float* ws2 = (const float*)d_in[8];
    const float* bs2 = (const float*)d_in[9];
    float* out = (float*)d_out;

    zero_kernel<<<1, 32>>>();
    gate_kernel<<<(NTOK * 32 + 255) / 256, 256>>>(x, gw);
    offsets_kernel<<<1, 1>>>();
    scatter_kernel<<<(2 * NTOK + 255) / 256, 256>>>();

    dim3 blk(256);
    // shared expert fc1: [8192,768] x [3072,768]^T -> gelu -> g_hs
    gemm_kernel<0, DIM, FDIM><<<dim3(NTOK / 128, FDIM / 64, 1), blk>>>(x, ws1, bs1, nullptr);
    // shared expert fc2: [8192,3072] x [768,3072]^T -> out (store, establishes base)
    gemm_kernel<1, FDIM, DIM><<<dim3(NTOK / 128, DIM / 64, 1), blk>>>(nullptr, ws2, bs2, out);
    // routed fc1 (gathered): per expert segment -> gelu -> g_h
    gemm_kernel<2, DIM, FDIM><<<dim3(NTOK / 128, FDIM / 64, NEXP), blk>>>(x, w1, b1, nullptr);
    // routed fc2: per expert segment -> weighted atomicAdd into out
    gemm_kernel<3, FDIM, DIM><<<dim3(NTOK / 128, DIM / 64, NEXP), blk>>>(nullptr, w2, b2, out);
}

// round 4
// speedup vs baseline: 2.1192x; 2.1192x over previous
#include <cuda_runtime.h>
#include <cuda_bf16.h>
#include <math.h>
#include <stdint.h>

#define NTOK 8192
#define DIM  768
#define FDIM 3072
#define NEXP 8
#define NSLOT (2*NTOK)

#define BM 128
#define BN 128
#define BK 32
#define SKB 80            // smem row stride in bytes (32 bf16 + 8 pad)
#define ABUF 10240        // 128*80
#define MMA_THREADS 256

// ---------------- device-global scratch ----------------
__device__ int   g_counts[NEXP];
__device__ int   g_counts2[NEXP];
__device__ int   g_offsets[NEXP + 1];
__device__ int   g_te[NSLOT];
__device__ float g_tw[NSLOT];
__device__ int   g_perm[NSLOT];
__device__ float g_permw[NSLOT];
__device__ int   g_slotmap[NSLOT];

__device__ __align__(256) __nv_bfloat16 g_x2[(size_t)NTOK * 3 * DIM];
__device__ __align__(256) __nv_bfloat16 g_w1b[(size_t)NEXP * FDIM * 3 * DIM];
__device__ __align__(256) __nv_bfloat16 g_w2b[(size_t)NEXP * DIM * 3 * FDIM];
__device__ __align__(256) __nv_bfloat16 g_ws1b[(size_t)FDIM * 3 * DIM];
__device__ __align__(256) __nv_bfloat16 g_ws2b[(size_t)DIM * 3 * FDIM];
__device__ __align__(256) __nv_bfloat16 g_hb[(size_t)NSLOT * 3 * FDIM];
__device__ __align__(256) __nv_bfloat16 g_hsb[(size_t)NTOK * 3 * FDIM];
__device__ __align__(256) float g_y[(size_t)NSLOT * DIM];

// ---------------- helpers ----------------
__device__ __forceinline__ uint32_t s2u(const void* p) {
    uint32_t a;
    asm("{ .reg .u64 t; cvta.to.shared.u64 t, %1; cvt.u32.u64 %0, t; }"
        : "=r"(a) : "l"(p));
    return a;
}

__device__ __forceinline__ void cp16(uint32_t dst, const void* src, bool pred) {
    int sz = pred ? 16 : 0;
    asm volatile("cp.async.cg.shared.global [%0], [%1], 16, %2;"
                 :: "r"(dst), "l"(src), "r"(sz) : "memory");
}
__device__ __forceinline__ void cp_commit() {
    asm volatile("cp.async.commit_group;" ::: "memory");
}
template <int N>
__device__ __forceinline__ void cp_wait() {
    asm volatile("cp.async.wait_group %0;" :: "n"(N) : "memory");
}

__device__ __forceinline__ void ldsm4(uint32_t (&r)[4], uint32_t addr) {
    asm volatile("ldmatrix.sync.aligned.m8n8.x4.shared.b16 {%0,%1,%2,%3}, [%4];"
                 : "=r"(r[0]), "=r"(r[1]), "=r"(r[2]), "=r"(r[3]) : "r"(addr));
}

__device__ __forceinline__ void mma16816(float (&c)[4], const uint32_t (&a)[4],
                                         uint32_t b0, uint32_t b1) {
    asm volatile(
        "mma.sync.aligned.m16n8k16.row.col.f32.bf16.bf16.f32 "
        "{%0,%1,%2,%3}, {%4,%5,%6,%7}, {%8,%9}, {%0,%1,%2,%3};"
        : "+f"(c[0]), "+f"(c[1]), "+f"(c[2]), "+f"(c[3])
        : "r"(a[0]), "r"(a[1]), "r"(a[2]), "r"(a[3]), "r"(b0), "r"(b1));
}

__device__ __forceinline__ float gelu_f(float v) {
    return 0.5f * v * (1.f + erff(v * 0.70710678118654752f));
}

// ---------------- small kernels ----------------
__global__ void zero_kernel() {
    int t = threadIdx.x;
    if (t < NEXP) { g_counts[t] = 0; g_counts2[t] = 0; }
}

__global__ void gate_kernel(const float* __restrict__ x,
                            const float* __restrict__ gw) {
    int gid  = blockIdx.x * blockDim.x + threadIdx.x;
    int tok  = gid >> 5;
    int lane = gid & 31;
    if (tok >= NTOK) return;

    const float* xr = x + (size_t)tok * DIM;
    float xv[24];
#pragma unroll
    for (int i = 0; i < 24; i++) xv[i] = xr[lane + 32 * i];

    float logit[NEXP];
#pragma unroll
    for (int e = 0; e < NEXP; e++) {
        const float* w = gw + e * DIM;
        float s = 0.f;
#pragma unroll
        for (int i = 0; i < 24; i++) s = fmaf(xv[i], w[lane + 32 * i], s);
#pragma unroll
        for (int o = 16; o > 0; o >>= 1) s += __shfl_down_sync(0xffffffffu, s, o);
        logit[e] = s;
    }
    if (lane == 0) {
        int i1 = 0;
#pragma unroll
        for (int e = 1; e < NEXP; e++) if (logit[e] > logit[i1]) i1 = e;
        int i2 = (i1 == 0) ? 1 : 0;
#pragma unroll
        for (int e = 0; e < NEXP; e++) {
            if (e == i1 || e == i2) continue;
            if (logit[e] > logit[i2]) i2 = e;
        }
        float e2    = expf(logit[i2] - logit[i1]);
        float denom = 1.f + e2;
        g_te[2 * tok]     = i1;
        g_te[2 * tok + 1] = i2;
        g_tw[2 * tok]     = 1.f / denom;
        g_tw[2 * tok + 1] = e2 / denom;
        atomicAdd(&g_counts[i1], 1);
        atomicAdd(&g_counts[i2], 1);
    }
}

__global__ void offsets_kernel() {
    int s = 0;
    g_offsets[0] = 0;
#pragma unroll
    for (int e = 0; e < NEXP; e++) { s += g_counts[e]; g_offsets[e + 1] = s; }
}

__global__ void scatter_kernel() {
    int t = blockIdx.x * blockDim.x + threadIdx.x;
    if (t >= NSLOT) return;
    int e   = g_te[t];
    int pos = g_offsets[e] + atomicAdd(&g_counts2[e], 1);
    g_perm[pos]  = t >> 1;
    g_permw[pos] = g_tw[t];
    g_slotmap[t] = pos;
}

// fp32 [R,K] -> bf16 [R,3K].
// ORDER 0 (activations): [hi | hi | lo]
// ORDER 1 (weights):     [hi | lo | hi]
// dot(seg_a, seg_b) = hi*hi + hi*lo + lo*hi  (lo*lo dropped, ~1e-5 rel)
template <int ORDER>
__global__ void split_kernel(const float* __restrict__ in,
                             __nv_bfloat16* __restrict__ out,
                             int K, long long total) {
    long long i4 = ((long long)blockIdx.x * blockDim.x + threadIdx.x) * 4;
    if (i4 >= total) return;
    long long r = i4 / K;
    int c = (int)(i4 - r * K);
    float4 v = *reinterpret_cast<const float4*>(in + i4);
    __nv_bfloat16 h0 = __float2bfloat16_rn(v.x);
    __nv_bfloat16 h1 = __float2bfloat16_rn(v.y);
    __nv_bfloat16 h2 = __float2bfloat16_rn(v.z);
    __nv_bfloat16 h3 = __float2bfloat16_rn(v.w);
    __nv_bfloat162 hp01; hp01.x = h0; hp01.y = h1;
    __nv_bfloat162 hp23; hp23.x = h2; hp23.y = h3;
    __nv_bfloat162 lp01;
    lp01.x = __float2bfloat16_rn(v.x - __bfloat162float(h0));
    lp01.y = __float2bfloat16_rn(v.y - __bfloat162float(h1));
    __nv_bfloat162 lp23;
    lp23.x = __float2bfloat16_rn(v.z - __bfloat162float(h2));
    lp23.y = __float2bfloat16_rn(v.w - __bfloat162float(h3));
    size_t base = (size_t)r * (3 * (size_t)K);
    size_t off_hi2 = (ORDER == 0) ? (size_t)K : (size_t)2 * K;
    size_t off_lo  = (ORDER == 0) ? (size_t)2 * K : (size_t)K;
    *reinterpret_cast<__nv_bfloat162*>(out + base + c)               = hp01;
    *reinterpret_cast<__nv_bfloat162*>(out + base + c + 2)           = hp23;
    *reinterpret_cast<__nv_bfloat162*>(out + base + off_hi2 + c)     = hp01;
    *reinterpret_cast<__nv_bfloat162*>(out + base + off_hi2 + c + 2) = hp23;
    *reinterpret_cast<__nv_bfloat162*>(out + base + off_lo + c)      = lp01;
    *reinterpret_cast<__nv_bfloat162*>(out + base + off_lo + c + 2)  = lp23;
}

// ---------------- mma.sync GEMM ----------------
// MODE 0: shared fc1 (A=g_x2, B=ws1b) -> gelu split -> g_hsb
// MODE 1: shared fc2 (A=g_hsb, B=ws2b) -> out (store + bias)
// MODE 2: routed fc1 (A=g_x2 gathered via g_perm, B=w1b[e]) -> gelu split -> g_hb
// MODE 3: routed fc2 (A=g_hb, B=w2b[e]) -> weighted store -> g_y
template <int MODE, int K3, int ND>
__global__ __launch_bounds__(MMA_THREADS)
void mma_kernel(const __nv_bfloat16* __restrict__ A,
                const __nv_bfloat16* __restrict__ Bw,
                const float* __restrict__ bias,
                float* __restrict__ outp) {
    const int e = blockIdx.z;
    int seg_start = 0, seg_len = NTOK;
    if (MODE >= 2) {
        seg_start = g_offsets[e];
        seg_len   = g_offsets[e + 1] - seg_start;
    }
    const int m0 = blockIdx.y * BM;
    if (m0 >= seg_len) return;
    const int n0 = blockIdx.x * BN;

    __shared__ __align__(128) char smem[4 * ABUF];   // A0,A1,B0,B1
    const uint32_t sbase = s2u(smem);

    const int tid  = threadIdx.x;
    const int wid  = tid >> 5;
    const int lane = tid & 31;
    const int wm   = wid >> 2;     // 0..1
    const int wn   = wid & 3;      // 0..3

    // ---- gmem row pointers for cp.async (2 A rows + 2 B rows per thread) ----
    const int lr = tid >> 2;       // 0..63
    const int cc = tid & 3;        // chunk col 0..3 (8 bf16 each)
    const __nv_bfloat16* aptr[2];
    bool av[2];
#pragma unroll
    for (int h = 0; h < 2; h++) {
        int gr = m0 + lr + h * 64;
        bool v = true;
        const __nv_bfloat16* p;
        if (MODE == 0 || MODE == 1) {
            p = A + (size_t)gr * K3;
        } else if (MODE == 2) {
            v = (gr < seg_len);
            int tok = v ? g_perm[seg_start + gr] : 0;
            p = A + (size_t)tok * K3;
        } else {
            v = (gr < seg_len);
            p = A + (size_t)(seg_start + (v ? gr : 0)) * K3;
        }
        aptr[h] = p + cc * 8;
        av[h]   = v;
    }
    const __nv_bfloat16* bptr[2];
#pragma unroll
    for (int h = 0; h < 2; h++)
        bptr[h] = Bw + ((size_t)e * ND + (n0 + lr + h * 64)) * K3 + cc * 8;

    const uint32_t sdst = (uint32_t)(lr * SKB + cc * 16);

    auto load_tile = [&](int kt, int buf) {
        const int k0 = kt * BK;
        uint32_t da = sbase + buf * ABUF + sdst;
        uint32_t db = sbase + 2 * ABUF + buf * ABUF + sdst;
        cp16(da,            aptr[0] + k0, av[0]);
        cp16(da + 64 * SKB, aptr[1] + k0, av[1]);
        cp16(db,            bptr[0] + k0, true);
        cp16(db + 64 * SKB, bptr[1] + k0, true);
    };

    // ---- ldmatrix base offsets ----
    const uint32_t aoff = (uint32_t)((wm * 64 + (lane & 15)) * SKB + (lane >> 4) * 16);
    const uint32_t boff = (uint32_t)((wn * 32 + (lane & 15)) * SKB + (lane >> 4) * 16)
                          + 2 * ABUF;

    float acc[4][4][4];
#pragma unroll
    for (int i = 0; i < 4; i++)
#pragma unroll
        for (int j = 0; j < 4; j++)
#pragma unroll
            for (int q = 0; q < 4; q++) acc[i][j][q] = 0.f;

    const int nt = K3 / BK;
    load_tile(0, 0);
    cp_commit();

    for (int t = 0; t < nt; t++) {
        const int b = t & 1;
        if (t + 1 < nt) {
            load_tile(t + 1, b ^ 1);
            cp_commit();
            cp_wait<1>();
        } else {
            cp_wait<0>();
        }
        __syncthreads();

        const uint32_t ab = sbase + b * ABUF + aoff;
        const uint32_t bb = sbase + b * ABUF + boff;
#pragma unroll
        for (int ks = 0; ks < 2; ks++) {
            uint32_t br[2][4];
            ldsm4(br[0], bb + ks * 32);
            ldsm4(br[1], bb + 1280 + ks * 32);
#pragma unroll
            for (int i = 0; i < 4; i++) {
                uint32_t ar[4];
                ldsm4(ar, ab + i * 1280 + ks * 32);
#pragma unroll
                for (int jn = 0; jn < 4; jn++) {
                    int jp = jn >> 1, sub = jn & 1;
                    mma16816(acc[i][jn], ar, br[jp][sub], br[jp][sub + 2]);
                }
            }
        }
        __syncthreads();
    }

    // ---- epilogue ----
    const int colb = wn * 32 + (lane & 3) * 2;
#pragma unroll
    for (int i = 0; i < 4; i++) {
#pragma unroll
        for (int half = 0; half < 2; half++) {
            const int rl = wm * 64 + i * 16 + (lane >> 2) + half * 8;
            const int gr = m0 + rl;
            if (MODE >= 2 && gr >= seg_len) continue;
            float wgt = 0.f;
            if (MODE == 3) wgt = g_permw[seg_start + gr];
#pragma unroll
            for (int jn = 0; jn < 4; jn++) {
                const int c = n0 + colb + jn * 8;
                float v0 = acc[i][jn][2 * half]     + bias[(size_t)e * ND + c];
                float v1 = acc[i][jn][2 * half + 1] + bias[(size_t)e * ND + c + 1];
                if (MODE == 0 || MODE == 2) {
                    v0 = gelu_f(v0); v1 = gelu_f(v1);
                    __nv_bfloat16 h0 = __float2bfloat16_rn(v0);
                    __nv_bfloat16 h1 = __float2bfloat16_rn(v1);
                    __nv_bfloat162 hp; hp.x = h0; hp.y = h1;
                    __nv_bfloat162 lp;
                    lp.x = __float2bfloat16_rn(v0 - __bfloat162float(h0));
                    lp.y = __float2bfloat16_rn(v1 - __bfloat162float(h1));
                    __nv_bfloat16* hout = (MODE == 0) ? g_hsb : g_hb;
                    size_t base = (MODE == 0) ? (size_t)gr * (3 * FDIM)
                                              : (size_t)(seg_start + gr) * (3 * FDIM);
                    *reinterpret_cast<__nv_bfloat162*>(hout + base + c)            = hp;
                    *reinterpret_cast<__nv_bfloat162*>(hout + base + FDIM + c)     = hp;
                    *reinterpret_cast<__nv_bfloat162*>(hout + base + 2 * FDIM + c) = lp;
                } else if (MODE == 1) {
                    float2 o; o.x = v0; o.y = v1;
                    *reinterpret_cast<float2*>(outp + (size_t)gr * DIM + c) = o;
                } else {
                    float2 o; o.x = wgt * v0; o.y = wgt * v1;
                    *reinterpret_cast<float2*>(g_y + (size_t)(seg_start + gr) * DIM + c) = o;
                }
            }
        }
    }
}

// out[tok] += y[slot0] + y[slot1]
__global__ void combine_kernel(float* __restrict__ out) {
    long long i = (long long)blockIdx.x * blockDim.x + threadIdx.x;
    const long long total = (long long)NTOK * DIM / 4;
    if (i >= total) return;
    int tok = (int)(i / (DIM / 4));
    int cc  = (int)(i % (DIM / 4));
    int s0 = g_slotmap[2 * tok];
    int s1 = g_slotmap[2 * tok + 1];
    float4 b  = reinterpret_cast<float4*>(out)[i];
    float4 y0 = *(reinterpret_cast<const float4*>(g_y + (size_t)s0 * DIM) + cc);
    float4 y1 = *(reinterpret_cast<const float4*>(g_y + (size_t)s1 * DIM) + cc);
    b.x += y0.x + y1.x;
    b.y += y0.y + y1.y;
    b.z += y0.z + y1.z;
    b.w += y0.w + y1.w;
    reinterpret_cast<float4*>(out)[i] = b;
}

// ---------------- launch ----------------
extern "C" void kernel_launch(void* const* d_in, const int* in_sizes, int n_in,
                              void* d_out, int out_size) {
    const float* x   = (const float*)d_in[0];
    const float* gw  = (const float*)d_in[1];
    const float* w1  = (const float*)d_in[2];
    const float* b1  = (const float*)d_in[3];
    const float* w2  = (const float*)d_in[4];
    const float* b2  = (const float*)d_in[5];
    const float* ws1 = (const float*)d_in[6];
    const float* bs1 = (const float*)d_in[7];
    const float* ws2 = (const float*)d_in[8];
    const float* bs2 = (const float*)d_in[9];
    float* out = (float*)d_out;

    void *px2, *pw1b, *pw2b, *pws1b, *pws2b, *phb, *phsb;
    cudaGetSymbolAddress(&px2,   g_x2);
    cudaGetSymbolAddress(&pw1b,  g_w1b);
    cudaGetSymbolAddress(&pw2b,  g_w2b);
    cudaGetSymbolAddress(&pws1b, g_ws1b);
    cudaGetSymbolAddress(&pws2b, g_ws2b);
    cudaGetSymbolAddress(&phb,   g_hb);
    cudaGetSymbolAddress(&phsb,  g_hsb);

    zero_kernel<<<1, 32>>>();
    gate_kernel<<<(NTOK * 32 + 255) / 256, 256>>>(x, gw);
    offsets_kernel<<<1, 1>>>();
    scatter_kernel<<<(NSLOT + 255) / 256, 256>>>();

    // bf16 splits: activations ORDER 0, weights ORDER 1
    {
        long long t;
        t = (long long)NTOK * DIM;
        split_kernel<0><<<(unsigned)((t / 4 + 255) / 256), 256>>>(x,   (__nv_bfloat16*)px2,   DIM,  t);
        t = (long long)NEXP * FDIM * DIM;
        split_kernel<1><<<(unsigned)((t / 4 + 255) / 256), 256>>>(w1,  (__nv_bfloat16*)pw1b,  DIM,  t);
        t = (long long)NEXP * DIM * FDIM;
        split_kernel<1><<<(unsigned)((t / 4 + 255) / 256), 256>>>(w2,  (__nv_bfloat16*)pw2b,  FDIM, t);
        t = (long long)FDIM * DIM;
        split_kernel<1><<<(unsigned)((t / 4 + 255) / 256), 256>>>(ws1, (__nv_bfloat16*)pws1b, DIM,  t);
        t = (long long)DIM * FDIM;
        split_kernel<1><<<(unsigned)((t / 4 + 255) / 256), 256>>>(ws2, (__nv_bfloat16*)pws2b, FDIM, t);
    }

    // GEMMs
    mma_kernel<0, 3 * DIM, FDIM>
        <<<dim3(FDIM / BN, NTOK / BM, 1), MMA_THREADS>>>(
            (const __nv_bfloat16*)px2, (const __nv_bfloat16*)pws1b, bs1, nullptr);
    mma_kernel<2, 3 * DIM, FDIM>
        <<<dim3(FDIM / BN, NSLOT / BM, NEXP), MMA_THREADS>>>(
            (const __nv_bfloat16*)px2, (const __nv_bfloat16*)pw1b, b1, nullptr);
    mma_kernel<1, 3 * FDIM, DIM>
        <<<dim3(DIM / BN, NTOK / BM, 1), MMA_THREADS>>>(
            (const __nv_bfloat16*)phsb, (const __nv_bfloat16*)pws2b, bs2, out);
    mma_kernel<3, 3 * FDIM, DIM>
        <<<dim3(DIM / BN, NSLOT / BM, NEXP), MMA_THREADS>>>(
            (const __nv_bfloat16*)phb, (const __nv_bfloat16*)pw2b, b2, nullptr);

    combine_kernel<<<(unsigned)(((long long)NTOK * DIM / 4 + 255) / 256), 256>>>(out);
}

// round 5
// speedup vs baseline: 3.3886x; 1.5990x over previous
#include <cuda_runtime.h>
#include <cuda_fp16.h>
#include <math.h>
#include <stdint.h>

#define NTOK 8192
#define DIM  768
#define FDIM 3072
#define NEXP 8
#define NSLOT (2*NTOK)

#define BM 128
#define BN 128
#define BK 32
#define SKB 80            // smem row stride bytes (32 fp16 + 8 pad)
#define OPBUF 10240       // 128*80 per operand
#define STGBUF 20480      // A+B per stage
#define NSTAGE 3
#define SMEM_DYN (NSTAGE*STGBUF)
#define MMA_THREADS 256

// ---------------- device-global scratch ----------------
__device__ int   g_counts[NEXP];
__device__ int   g_counts2[NEXP];
__device__ int   g_offsets[NEXP + 1];
__device__ int   g_te[NSLOT];
__device__ float g_tw[NSLOT];
__device__ int   g_perm[NSLOT];
__device__ float g_permw[NSLOT];
__device__ int   g_slotmap[NSLOT];

__device__ __align__(256) __half g_x2[(size_t)NTOK * 2 * DIM];            // [hi|lo]
__device__ __align__(256) __half g_w1h[(size_t)NEXP * FDIM * DIM];        // hi only
__device__ __align__(256) __half g_w2h[(size_t)NEXP * DIM * FDIM];
__device__ __align__(256) __half g_ws1h[(size_t)FDIM * DIM];
__device__ __align__(256) __half g_ws2h[(size_t)DIM * FDIM];
__device__ __align__(256) __half g_hb[(size_t)NSLOT * 2 * FDIM];          // [hi|lo]
__device__ __align__(256) __half g_hsb[(size_t)NTOK * 2 * FDIM];
__device__ __align__(256) float  g_y[(size_t)NSLOT * DIM];

// ---------------- helpers ----------------
__device__ __forceinline__ uint32_t s2u(const void* p) {
    uint32_t a;
    asm("{ .reg .u64 t; cvta.to.shared.u64 t, %1; cvt.u32.u64 %0, t; }"
        : "=r"(a) : "l"(p));
    return a;
}

__device__ __forceinline__ void cp16(uint32_t dst, const void* src, bool pred) {
    int sz = pred ? 16 : 0;
    asm volatile("cp.async.cg.shared.global [%0], [%1], 16, %2;"
                 :: "r"(dst), "l"(src), "r"(sz) : "memory");
}
__device__ __forceinline__ void cp_commit() {
    asm volatile("cp.async.commit_group;" ::: "memory");
}
template <int N>
__device__ __forceinline__ void cp_wait() {
    asm volatile("cp.async.wait_group %0;" :: "n"(N) : "memory");
}

__device__ __forceinline__ void ldsm4(uint32_t (&r)[4], uint32_t addr) {
    asm volatile("ldmatrix.sync.aligned.m8n8.x4.shared.b16 {%0,%1,%2,%3}, [%4];"
                 : "=r"(r[0]), "=r"(r[1]), "=r"(r[2]), "=r"(r[3]) : "r"(addr));
}

__device__ __forceinline__ void mma16816(float (&c)[4], const uint32_t (&a)[4],
                                         uint32_t b0, uint32_t b1) {
    asm volatile(
        "mma.sync.aligned.m16n8k16.row.col.f32.f16.f16.f32 "
        "{%0,%1,%2,%3}, {%4,%5,%6,%7}, {%8,%9}, {%0,%1,%2,%3};"
        : "+f"(c[0]), "+f"(c[1]), "+f"(c[2]), "+f"(c[3])
        : "r"(a[0]), "r"(a[1]), "r"(a[2]), "r"(a[3]), "r"(b0), "r"(b1));
}

__device__ __forceinline__ float gelu_f(float v) {
    return 0.5f * v * (1.f + erff(v * 0.70710678118654752f));
}

// ---------------- small kernels ----------------
__global__ void zero_kernel() {
    int t = threadIdx.x;
    if (t < NEXP) { g_counts[t] = 0; g_counts2[t] = 0; }
}

__global__ void gate_kernel(const float* __restrict__ x,
                            const float* __restrict__ gw) {
    int gid  = blockIdx.x * blockDim.x + threadIdx.x;
    int tok  = gid >> 5;
    int lane = gid & 31;
    if (tok >= NTOK) return;

    const float* xr = x + (size_t)tok * DIM;
    float xv[24];
#pragma unroll
    for (int i = 0; i < 24; i++) xv[i] = xr[lane + 32 * i];

    float logit[NEXP];
#pragma unroll
    for (int e = 0; e < NEXP; e++) {
        const float* w = gw + e * DIM;
        float s = 0.f;
#pragma unroll
        for (int i = 0; i < 24; i++) s = fmaf(xv[i], w[lane + 32 * i], s);
#pragma unroll
        for (int o = 16; o > 0; o >>= 1) s += __shfl_down_sync(0xffffffffu, s, o);
        logit[e] = s;
    }
    if (lane == 0) {
        int i1 = 0;
#pragma unroll
        for (int e = 1; e < NEXP; e++) if (logit[e] > logit[i1]) i1 = e;
        int i2 = (i1 == 0) ? 1 : 0;
#pragma unroll
        for (int e = 0; e < NEXP; e++) {
            if (e == i1 || e == i2) continue;
            if (logit[e] > logit[i2]) i2 = e;
        }
        float e2    = expf(logit[i2] - logit[i1]);
        float denom = 1.f + e2;
        g_te[2 * tok]     = i1;
        g_te[2 * tok + 1] = i2;
        g_tw[2 * tok]     = 1.f / denom;
        g_tw[2 * tok + 1] = e2 / denom;
        atomicAdd(&g_counts[i1], 1);
        atomicAdd(&g_counts[i2], 1);
    }
}

__global__ void offsets_kernel() {
    int s = 0;
    g_offsets[0] = 0;
#pragma unroll
    for (int e = 0; e < NEXP; e++) { s += g_counts[e]; g_offsets[e + 1] = s; }
}

__global__ void scatter_kernel() {
    int t = blockIdx.x * blockDim.x + threadIdx.x;
    if (t >= NSLOT) return;
    int e   = g_te[t];
    int pos = g_offsets[e] + atomicAdd(&g_counts2[e], 1);
    g_perm[pos]  = t >> 1;
    g_permw[pos] = g_tw[t];
    g_slotmap[t] = pos;
}

// activations fp32 [R,K] -> fp16 [R,2K] = [hi | lo]
__global__ void split_act_kernel(const float* __restrict__ in,
                                 __half* __restrict__ out,
                                 int K, long long total) {
    long long i4 = ((long long)blockIdx.x * blockDim.x + threadIdx.x) * 4;
    if (i4 >= total) return;
    long long r = i4 / K;
    int c = (int)(i4 - r * K);
    float4 v = *reinterpret_cast<const float4*>(in + i4);
    __half h0 = __float2half_rn(v.x), h1 = __float2half_rn(v.y);
    __half h2 = __float2half_rn(v.z), h3 = __float2half_rn(v.w);
    __half2 hp01; hp01.x = h0; hp01.y = h1;
    __half2 hp23; hp23.x = h2; hp23.y = h3;
    __half2 lp01, lp23;
    lp01.x = __float2half_rn(v.x - __half2float(h0));
    lp01.y = __float2half_rn(v.y - __half2float(h1));
    lp23.x = __float2half_rn(v.z - __half2float(h2));
    lp23.y = __float2half_rn(v.w - __half2float(h3));
    size_t base = (size_t)r * (2 * (size_t)K);
    *reinterpret_cast<__half2*>(out + base + c)         = hp01;
    *reinterpret_cast<__half2*>(out + base + c + 2)     = hp23;
    *reinterpret_cast<__half2*>(out + base + K + c)     = lp01;
    *reinterpret_cast<__half2*>(out + base + K + c + 2) = lp23;
}

// weights fp32 -> fp16 flat
__global__ void conv_w_kernel(const float* __restrict__ in,
                              __half* __restrict__ out, long long total) {
    long long i4 = ((long long)blockIdx.x * blockDim.x + threadIdx.x) * 4;
    if (i4 >= total) return;
    float4 v = *reinterpret_cast<const float4*>(in + i4);
    __half2 a, b;
    a.x = __float2half_rn(v.x); a.y = __float2half_rn(v.y);
    b.x = __float2half_rn(v.z); b.y = __float2half_rn(v.w);
    *reinterpret_cast<__half2*>(out + i4)     = a;
    *reinterpret_cast<__half2*>(out + i4 + 2) = b;
}

// ---------------- mma.sync GEMM (merged routed+shared) ----------------
// PHASE 1: fc1.  A = x2 [hi|lo] (routed: gathered via g_perm; z==8: direct)
//                B = w1h / ws1h (hi only, K-modular)  -> gelu -> [hi|lo] hidden
// PHASE 2: fc2.  A = g_hb / g_hsb [hi|lo], B = w2h / ws2h
//                z==8 -> outp (store), z<8 -> g_y (weighted store)
template <int PHASE, int KB, int ND>
__global__ __launch_bounds__(MMA_THREADS, 2)
void mma_kernel(const __half* __restrict__ Ar, const __half* __restrict__ Ash,
                const __half* __restrict__ Br, const __half* __restrict__ Bsh,
                const float* __restrict__ biasR, const float* __restrict__ biasS,
                float* __restrict__ outp) {
    constexpr int KA = 2 * KB;
    const int e = blockIdx.z;              // 0..7 routed, 8 = shared expert
    const bool se = (e == NEXP);
    int seg_start = 0, seg_len = NTOK;
    if (!se) {
        seg_start = g_offsets[e];
        seg_len   = g_offsets[e + 1] - seg_start;
    }
    const int m0 = blockIdx.y * BM;
    if (m0 >= seg_len) return;
    const int n0 = blockIdx.x * BN;

    extern __shared__ __align__(128) char smem[];
    const uint32_t sbase = s2u(smem);

    const int tid  = threadIdx.x;
    const int wid  = tid >> 5;
    const int lane = tid & 31;
    const int wm   = wid >> 2;
    const int wn   = wid & 3;

    // gmem pointers for cp.async
    const int lr = tid >> 2;     // 0..63
    const int cc = tid & 3;      // 8-halfword chunk
    const __half* aptr[2];
    bool av[2];
#pragma unroll
    for (int h = 0; h < 2; h++) {
        int gr = m0 + lr + h * 64;
        bool v = (gr < seg_len);
        const __half* p;
        if (se) {
            p = Ash + (size_t)(v ? gr : 0) * KA;
        } else if (PHASE == 1) {
            int tok = v ? g_perm[seg_start + gr] : 0;
            p = Ar + (size_t)tok * KA;
        } else {
            p = Ar + (size_t)(seg_start + (v ? gr : 0)) * KA;
        }
        aptr[h] = p + cc * 8;
        av[h]   = v;
    }
    const __half* bptr[2];
#pragma unroll
    for (int h = 0; h < 2; h++) {
        int brow = n0 + lr + h * 64;
        bptr[h] = (se ? Bsh + (size_t)brow * KB
                      : Br + ((size_t)e * ND + brow) * KB) + cc * 8;
    }

    const uint32_t sdst = (uint32_t)(lr * SKB + cc * 16);

    auto load_tile = [&](int kt, int buf) {
        const int k0 = kt * BK;
        const int bk = (k0 >= KB) ? k0 - KB : k0;   // B is K-modular (hi only)
        uint32_t da = sbase + buf * STGBUF + sdst;
        uint32_t db = da + OPBUF;
        cp16(da,            aptr[0] + k0, av[0]);
        cp16(da + 64 * SKB, aptr[1] + k0, av[1]);
        cp16(db,            bptr[0] + bk, true);
        cp16(db + 64 * SKB, bptr[1] + bk, true);
    };

    const uint32_t aoff = (uint32_t)((wm * 64 + (lane & 15)) * SKB + (lane >> 4) * 16);
    const uint32_t boff = (uint32_t)((wn * 32 + (lane & 15)) * SKB + (lane >> 4) * 16)
                          + OPBUF;

    float acc[4][4][4];
#pragma unroll
    for (int i = 0; i < 4; i++)
#pragma unroll
        for (int j = 0; j < 4; j++)
#pragma unroll
            for (int q = 0; q < 4; q++) acc[i][j][q] = 0.f;

    const int nt = KA / BK;
    load_tile(0, 0); cp_commit();
    load_tile(1, 1); cp_commit();

    int buf = 0;
    for (int t = 0; t < nt; t++) {
        cp_wait<1>();
        __syncthreads();

        const uint32_t ab = sbase + buf * STGBUF + aoff;
        const uint32_t bb = sbase + buf * STGBUF + boff;
#pragma unroll
        for (int ks = 0; ks < 2; ks++) {
            uint32_t br[2][4];
            ldsm4(br[0], bb + ks * 32);
            ldsm4(br[1], bb + 1280 + ks * 32);
#pragma unroll
            for (int i = 0; i < 4; i++) {
                uint32_t ar[4];
                ldsm4(ar, ab + i * 1280 + ks * 32);
#pragma unroll
                for (int jn = 0; jn < 4; jn++) {
                    int jp = jn >> 1, sub = jn & 1;
                    mma16816(acc[i][jn], ar, br[jp][sub], br[jp][sub + 2]);
                }
            }
        }
        if (t + 2 < nt) load_tile(t + 2, (t + 2) % NSTAGE);
        cp_commit();
        buf = (buf + 1 == NSTAGE) ? 0 : buf + 1;
    }

    // ---- epilogue ----
    const float* bias = se ? biasS : biasR + (size_t)e * ND;
    const int colb = wn * 32 + (lane & 3) * 2;
#pragma unroll
    for (int i = 0; i < 4; i++) {
#pragma unroll
        for (int half = 0; half < 2; half++) {
            const int rl = wm * 64 + i * 16 + (lane >> 2) + half * 8;
            const int gr = m0 + rl;
            if (gr >= seg_len) continue;
            float wgt = 0.f;
            if (PHASE == 2 && !se) wgt = g_permw[seg_start + gr];
#pragma unroll
            for (int jn = 0; jn < 4; jn++) {
                const int c = n0 + colb + jn * 8;
                float v0 = acc[i][jn][2 * half]     + bias[c];
                float v1 = acc[i][jn][2 * half + 1] + bias[c + 1];
                if (PHASE == 1) {
                    v0 = gelu_f(v0); v1 = gelu_f(v1);
                    __half h0 = __float2half_rn(v0);
                    __half h1 = __float2half_rn(v1);
                    __half2 hp; hp.x = h0; hp.y = h1;
                    __half2 lp;
                    lp.x = __float2half_rn(v0 - __half2float(h0));
                    lp.y = __float2half_rn(v1 - __half2float(h1));
                    __half* hout = se ? g_hsb : g_hb;
                    size_t base = se ? (size_t)gr * (2 * FDIM)
                                     : (size_t)(seg_start + gr) * (2 * FDIM);
                    *reinterpret_cast<__half2*>(hout + base + c)        = hp;
                    *reinterpret_cast<__half2*>(hout + base + FDIM + c) = lp;
                } else if (se) {
                    float2 o; o.x = v0; o.y = v1;
                    *reinterpret_cast<float2*>(outp + (size_t)gr * DIM + c) = o;
                } else {
                    float2 o; o.x = wgt * v0; o.y = wgt * v1;
                    *reinterpret_cast<float2*>(g_y + (size_t)(seg_start + gr) * DIM + c) = o;
                }
            }
        }
    }
}

// out[tok] += y[slot0] + y[slot1]
__global__ void combine_kernel(float* __restrict__ out) {
    long long i = (long long)blockIdx.x * blockDim.x + threadIdx.x;
    const long long total = (long long)NTOK * DIM / 4;
    if (i >= total) return;
    int tok = (int)(i / (DIM / 4));
    int cc  = (int)(i % (DIM / 4));
    int s0 = g_slotmap[2 * tok];
    int s1 = g_slotmap[2 * tok + 1];
    float4 b  = reinterpret_cast<float4*>(out)[i];
    float4 y0 = *(reinterpret_cast<const float4*>(g_y + (size_t)s0 * DIM) + cc);
    float4 y1 = *(reinterpret_cast<const float4*>(g_y + (size_t)s1 * DIM) + cc);
    b.x += y0.x + y1.x;
    b.y += y0.y + y1.y;
    b.z += y0.z + y1.z;
    b.w += y0.w + y1.w;
    reinterpret_cast<float4*>(out)[i] = b;
}

// ---------------- launch ----------------
extern "C" void kernel_launch(void* const* d_in, const int* in_sizes, int n_in,
                              void* d_out, int out_size) {
    const float* x   = (const float*)d_in[0];
    const float* gw  = (const float*)d_in[1];
    const float* w1  = (const float*)d_in[2];
    const float* b1  = (const float*)d_in[3];
    const float* w2  = (const float*)d_in[4];
    const float* b2  = (const float*)d_in[5];
    const float* ws1 = (const float*)d_in[6];
    const float* bs1 = (const float*)d_in[7];
    const float* ws2 = (const float*)d_in[8];
    const float* bs2 = (const float*)d_in[9];
    float* out = (float*)d_out;

    void *px2, *pw1h, *pw2h, *pws1h, *pws2h, *phb, *phsb;
    cudaGetSymbolAddress(&px2,   g_x2);
    cudaGetSymbolAddress(&pw1h,  g_w1h);
    cudaGetSymbolAddress(&pw2h,  g_w2h);
    cudaGetSymbolAddress(&pws1h, g_ws1h);
    cudaGetSymbolAddress(&pws2h, g_ws2h);
    cudaGetSymbolAddress(&phb,   g_hb);
    cudaGetSymbolAddress(&phsb,  g_hsb);

    cudaFuncSetAttribute(mma_kernel<1, DIM, FDIM>,
                         cudaFuncAttributeMaxDynamicSharedMemorySize, SMEM_DYN);
    cudaFuncSetAttribute(mma_kernel<2, FDIM, DIM>,
                         cudaFuncAttributeMaxDynamicSharedMemorySize, SMEM_DYN);

    zero_kernel<<<1, 32>>>();
    gate_kernel<<<(NTOK * 32 + 255) / 256, 256>>>(x, gw);
    offsets_kernel<<<1, 1>>>();
    scatter_kernel<<<(NSLOT + 255) / 256, 256>>>();

    {
        long long t;
        t = (long long)NTOK * DIM;
        split_act_kernel<<<(unsigned)((t / 4 + 255) / 256), 256>>>(x, (__half*)px2, DIM, t);
        t = (long long)NEXP * FDIM * DIM;
        conv_w_kernel<<<(unsigned)((t / 4 + 255) / 256), 256>>>(w1,  (__half*)pw1h,  t);
        t = (long long)NEXP * DIM * FDIM;
        conv_w_kernel<<<(unsigned)((t / 4 + 255) / 256), 256>>>(w2,  (__half*)pw2h,  t);
        t = (long long)FDIM * DIM;
        conv_w_kernel<<<(unsigned)((t / 4 + 255) / 256), 256>>>(ws1, (__half*)pws1h, t);
        t = (long long)DIM * FDIM;
        conv_w_kernel<<<(unsigned)((t / 4 + 255) / 256), 256>>>(ws2, (__half*)pws2h, t);
    }

    // fc1: z = 0..7 routed experts, z = 8 shared expert
    mma_kernel<1, DIM, FDIM>
        <<<dim3(FDIM / BN, NSLOT / BM, NEXP + 1), MMA_THREADS, SMEM_DYN>>>(
            (const __half*)px2, (const __half*)px2,
            (const __half*)pw1h, (const __half*)pws1h, b1, bs1, nullptr);
    // fc2
    mma_kernel<2, FDIM, DIM>
        <<<dim3(DIM / BN, NSLOT / BM, NEXP + 1), MMA_THREADS, SMEM_DYN>>>(
            (const __half*)phb, (const __half*)phsb,
            (const __half*)pw2h, (const __half*)pws2h, b2, bs2, out);

    combine_kernel<<<(unsigned)(((long long)NTOK * DIM / 4 + 255) / 256), 256>>>(out);
}

// round 6
// speedup vs baseline: 6.8534x; 2.0225x over previous
#include <cuda_runtime.h>
#include <cuda_fp16.h>
#include <math.h>
#include <stdint.h>

#define NTOK 8192
#define DIM  768
#define FDIM 3072
#define NEXP 8
#define NSLOT (2*NTOK)

#define BM 128
#define BN 128
#define BK 32
#define SKB 80            // smem row stride bytes (32 fp16 + 8 pad)
#define OPBUF 10240       // 128*80 per operand
#define STGBUF 20480      // A+B per stage
#define NSTAGE 4
#define SMEM_DYN (NSTAGE*STGBUF)
#define MMA_THREADS 256

// ---------------- device-global scratch ----------------
__device__ int   g_counts[NEXP];
__device__ int   g_counts2[NEXP];
__device__ int   g_offsets[NEXP + 1];
__device__ int   g_te[NSLOT];
__device__ float g_tw[NSLOT];
__device__ int   g_perm[NSLOT];
__device__ float g_permw[NSLOT];
__device__ int   g_slotmap[NSLOT];

__device__ __align__(256) __half g_xh[(size_t)NTOK * DIM];
__device__ __align__(256) __half g_w1h[(size_t)NEXP * FDIM * DIM];
__device__ __align__(256) __half g_w2h[(size_t)NEXP * DIM * FDIM];
__device__ __align__(256) __half g_ws1h[(size_t)FDIM * DIM];
__device__ __align__(256) __half g_ws2h[(size_t)DIM * FDIM];
__device__ __align__(256) __half g_hb[(size_t)NSLOT * FDIM];
__device__ __align__(256) __half g_hsb[(size_t)NTOK * FDIM];
__device__ __align__(256) float  g_y[(size_t)NSLOT * DIM];

// ---------------- helpers ----------------
__device__ __forceinline__ uint32_t s2u(const void* p) {
    uint32_t a;
    asm("{ .reg .u64 t; cvta.to.shared.u64 t, %1; cvt.u32.u64 %0, t; }"
        : "=r"(a) : "l"(p));
    return a;
}

__device__ __forceinline__ void cp16(uint32_t dst, const void* src, bool pred) {
    int sz = pred ? 16 : 0;
    asm volatile("cp.async.cg.shared.global [%0], [%1], 16, %2;"
                 :: "r"(dst), "l"(src), "r"(sz) : "memory");
}
__device__ __forceinline__ void cp_commit() {
    asm volatile("cp.async.commit_group;" ::: "memory");
}
template <int N>
__device__ __forceinline__ void cp_wait() {
    asm volatile("cp.async.wait_group %0;" :: "n"(N) : "memory");
}

__device__ __forceinline__ void ldsm4(uint32_t (&r)[4], uint32_t addr) {
    asm volatile("ldmatrix.sync.aligned.m8n8.x4.shared.b16 {%0,%1,%2,%3}, [%4];"
                 : "=r"(r[0]), "=r"(r[1]), "=r"(r[2]), "=r"(r[3]) : "r"(addr));
}

__device__ __forceinline__ void mma16816(float (&c)[4], const uint32_t (&a)[4],
                                         uint32_t b0, uint32_t b1) {
    asm volatile(
        "mma.sync.aligned.m16n8k16.row.col.f32.f16.f16.f32 "
        "{%0,%1,%2,%3}, {%4,%5,%6,%7}, {%8,%9}, {%0,%1,%2,%3};"
        : "+f"(c[0]), "+f"(c[1]), "+f"(c[2]), "+f"(c[3])
        : "r"(a[0]), "r"(a[1]), "r"(a[2]), "r"(a[3]), "r"(b0), "r"(b1));
}

__device__ __forceinline__ float gelu_f(float v) {
    return 0.5f * v * (1.f + erff(v * 0.70710678118654752f));
}

// ---------------- small kernels ----------------
__global__ void zero_kernel() {
    int t = threadIdx.x;
    if (t < NEXP) { g_counts[t] = 0; g_counts2[t] = 0; }
}

__global__ void gate_kernel(const float* __restrict__ x,
                            const float* __restrict__ gw) {
    int gid  = blockIdx.x * blockDim.x + threadIdx.x;
    int tok  = gid >> 5;
    int lane = gid & 31;
    if (tok >= NTOK) return;

    const float* xr = x + (size_t)tok * DIM;
    float xv[24];
#pragma unroll
    for (int i = 0; i < 24; i++) xv[i] = xr[lane + 32 * i];

    float logit[NEXP];
#pragma unroll
    for (int e = 0; e < NEXP; e++) {
        const float* w = gw + e * DIM;
        float s = 0.f;
#pragma unroll
        for (int i = 0; i < 24; i++) s = fmaf(xv[i], w[lane + 32 * i], s);
#pragma unroll
        for (int o = 16; o > 0; o >>= 1) s += __shfl_down_sync(0xffffffffu, s, o);
        logit[e] = s;
    }
    if (lane == 0) {
        int i1 = 0;
#pragma unroll
        for (int e = 1; e < NEXP; e++) if (logit[e] > logit[i1]) i1 = e;
        int i2 = (i1 == 0) ? 1 : 0;
#pragma unroll
        for (int e = 0; e < NEXP; e++) {
            if (e == i1 || e == i2) continue;
            if (logit[e] > logit[i2]) i2 = e;
        }
        float e2    = expf(logit[i2] - logit[i1]);
        float denom = 1.f + e2;
        g_te[2 * tok]     = i1;
        g_te[2 * tok + 1] = i2;
        g_tw[2 * tok]     = 1.f / denom;
        g_tw[2 * tok + 1] = e2 / denom;
        atomicAdd(&g_counts[i1], 1);
        atomicAdd(&g_counts[i2], 1);
    }
}

__global__ void offsets_kernel() {
    int s = 0;
    g_offsets[0] = 0;
#pragma unroll
    for (int e = 0; e < NEXP; e++) { s += g_counts[e]; g_offsets[e + 1] = s; }
}

__global__ void scatter_kernel() {
    int t = blockIdx.x * blockDim.x + threadIdx.x;
    if (t >= NSLOT) return;
    int e   = g_te[t];
    int pos = g_offsets[e] + atomicAdd(&g_counts2[e], 1);
    g_perm[pos]  = t >> 1;
    g_permw[pos] = g_tw[t];
    g_slotmap[t] = pos;
}

// fp32 -> fp16 flat
__global__ void conv_h_kernel(const float* __restrict__ in,
                              __half* __restrict__ out, long long total) {
    long long i4 = ((long long)blockIdx.x * blockDim.x + threadIdx.x) * 4;
    if (i4 >= total) return;
    float4 v = *reinterpret_cast<const float4*>(in + i4);
    __half2 a, b;
    a.x = __float2half_rn(v.x); a.y = __float2half_rn(v.y);
    b.x = __float2half_rn(v.z); b.y = __float2half_rn(v.w);
    *reinterpret_cast<__half2*>(out + i4)     = a;
    *reinterpret_cast<__half2*>(out + i4 + 2) = b;
}

// ---------------- mma.sync GEMM (merged routed+shared) ----------------
// PHASE 1: fc1.  A = g_xh (routed: gathered via g_perm; z==8: direct)
//                B = w1h / ws1h  -> gelu -> fp16 hidden
// PHASE 2: fc2.  A = g_hb / g_hsb, B = w2h / ws2h
//                z==8 -> outp (store), z<8 -> g_y (weighted store)
template <int PHASE, int KD, int ND>
__global__ __launch_bounds__(MMA_THREADS, 2)
void mma_kernel(const __half* __restrict__ Ar, const __half* __restrict__ Ash,
                const __half* __restrict__ Br, const __half* __restrict__ Bsh,
                const float* __restrict__ biasR, const float* __restrict__ biasS,
                float* __restrict__ outp) {
    const int e = blockIdx.z;              // 0..7 routed, 8 = shared expert
    const bool se = (e == NEXP);
    int seg_start = 0, seg_len = NTOK;
    if (!se) {
        seg_start = g_offsets[e];
        seg_len   = g_offsets[e + 1] - seg_start;
    }
    const int m0 = blockIdx.y * BM;
    if (m0 >= seg_len) return;
    const int n0 = blockIdx.x * BN;

    extern __shared__ __align__(128) char smem[];
    const uint32_t sbase = s2u(smem);

    const int tid  = threadIdx.x;
    const int wid  = tid >> 5;
    const int lane = tid & 31;
    const int wm   = wid >> 2;
    const int wn   = wid & 3;

    // gmem pointers for cp.async
    const int lr = tid >> 2;     // 0..63
    const int cc = tid & 3;      // 8-halfword chunk
    const __half* aptr[2];
    bool av[2];
#pragma unroll
    for (int h = 0; h < 2; h++) {
        int gr = m0 + lr + h * 64;
        bool v = (gr < seg_len);
        const __half* p;
        if (se) {
            p = Ash + (size_t)(v ? gr : 0) * KD;
        } else if (PHASE == 1) {
            int tok = v ? g_perm[seg_start + gr] : 0;
            p = Ar + (size_t)tok * KD;
        } else {
            p = Ar + (size_t)(seg_start + (v ? gr : 0)) * KD;
        }
        aptr[h] = p + cc * 8;
        av[h]   = v;
    }
    const __half* bptr[2];
#pragma unroll
    for (int h = 0; h < 2; h++) {
        int brow = n0 + lr + h * 64;
        bptr[h] = (se ? Bsh + (size_t)brow * KD
                      : Br + ((size_t)e * ND + brow) * KD) + cc * 8;
    }

    const uint32_t sdst = (uint32_t)(lr * SKB + cc * 16);

    auto load_tile = [&](int kt, int buf) {
        const int k0 = kt * BK;
        uint32_t da = sbase + buf * STGBUF + sdst;
        uint32_t db = da + OPBUF;
        cp16(da,            aptr[0] + k0, av[0]);
        cp16(da + 64 * SKB, aptr[1] + k0, av[1]);
        cp16(db,            bptr[0] + k0, true);
        cp16(db + 64 * SKB, bptr[1] + k0, true);
    };

    const uint32_t aoff = (uint32_t)((wm * 64 + (lane & 15)) * SKB + (lane >> 4) * 16);
    const uint32_t boff = (uint32_t)((wn * 32 + (lane & 15)) * SKB + (lane >> 4) * 16)
                          + OPBUF;

    float acc[4][4][4];
#pragma unroll
    for (int i = 0; i < 4; i++)
#pragma unroll
        for (int j = 0; j < 4; j++)
#pragma unroll
            for (int q = 0; q < 4; q++) acc[i][j][q] = 0.f;

    const int nt = KD / BK;
    load_tile(0, 0); cp_commit();
    load_tile(1, 1); cp_commit();
    load_tile(2, 2); cp_commit();

    int buf = 0;
    for (int t = 0; t < nt; t++) {
        cp_wait<2>();
        __syncthreads();

        const uint32_t ab = sbase + buf * STGBUF + aoff;
        const uint32_t bb = sbase + buf * STGBUF + boff;
#pragma unroll
        for (int ks = 0; ks < 2; ks++) {
            uint32_t br[2][4];
            ldsm4(br[0], bb + ks * 32);
            ldsm4(br[1], bb + 1280 + ks * 32);
#pragma unroll
            for (int i = 0; i < 4; i++) {
                uint32_t ar[4];
                ldsm4(ar, ab + i * 1280 + ks * 32);
#pragma unroll
                for (int jn = 0; jn < 4; jn++) {
                    int jp = jn >> 1, sub = jn & 1;
                    mma16816(acc[i][jn], ar, br[jp][sub], br[jp][sub + 2]);
                }
            }
        }
        if (t + 3 < nt) load_tile(t + 3, (t + 3) % NSTAGE);
        cp_commit();
        buf = (buf + 1 == NSTAGE) ? 0 : buf + 1;
    }

    // ---- epilogue ----
    const float* bias = se ? biasS : biasR + (size_t)e * ND;
    const int colb = wn * 32 + (lane & 3) * 2;
#pragma unroll
    for (int i = 0; i < 4; i++) {
#pragma unroll
        for (int half = 0; half < 2; half++) {
            const int rl = wm * 64 + i * 16 + (lane >> 2) + half * 8;
            const int gr = m0 + rl;
            if (gr >= seg_len) continue;
            float wgt = 0.f;
            if (PHASE == 2 && !se) wgt = g_permw[seg_start + gr];
#pragma unroll
            for (int jn = 0; jn < 4; jn++) {
                const int c = n0 + colb + jn * 8;
                float v0 = acc[i][jn][2 * half]     + bias[c];
                float v1 = acc[i][jn][2 * half + 1] + bias[c + 1];
                if (PHASE == 1) {
                    v0 = gelu_f(v0); v1 = gelu_f(v1);
                    __half2 hp;
                    hp.x = __float2half_rn(v0);
                    hp.y = __float2half_rn(v1);
                    __half* hout = se ? g_hsb : g_hb;
                    size_t base = se ? (size_t)gr * FDIM
                                     : (size_t)(seg_start + gr) * FDIM;
                    *reinterpret_cast<__half2*>(hout + base + c) = hp;
                } else if (se) {
                    float2 o; o.x = v0; o.y = v1;
                    *reinterpret_cast<float2*>(outp + (size_t)gr * DIM + c) = o;
                } else {
                    float2 o; o.x = wgt * v0; o.y = wgt * v1;
                    *reinterpret_cast<float2*>(g_y + (size_t)(seg_start + gr) * DIM + c) = o;
                }
            }
        }
    }
}

// out[tok] += y[slot0] + y[slot1]
__global__ void combine_kernel(float* __restrict__ out) {
    long long i = (long long)blockIdx.x * blockDim.x + threadIdx.x;
    const long long total = (long long)NTOK * DIM / 4;
    if (i >= total) return;
    int tok = (int)(i / (DIM / 4));
    int cc  = (int)(i % (DIM / 4));
    int s0 = g_slotmap[2 * tok];
    int s1 = g_slotmap[2 * tok + 1];
    float4 b  = reinterpret_cast<float4*>(out)[i];
    float4 y0 = *(reinterpret_cast<const float4*>(g_y + (size_t)s0 * DIM) + cc);
    float4 y1 = *(reinterpret_cast<const float4*>(g_y + (size_t)s1 * DIM) + cc);
    b.x += y0.x + y1.x;
    b.y += y0.y + y1.y;
    b.z += y0.z + y1.z;
    b.w += y0.w + y1.w;
    reinterpret_cast<float4*>(out)[i] = b;
}

// ---------------- launch ----------------
extern "C" void kernel_launch(void* const* d_in, const int* in_sizes, int n_in,
                              void* d_out, int out_size) {
    const float* x   = (const float*)d_in[0];
    const float* gw  = (const float*)d_in[1];
    const float* w1  = (const float*)d_in[2];
    const float* b1  = (const float*)d_in[3];
    const float* w2  = (const float*)d_in[4];
    const float* b2  = (const float*)d_in[5];
    const float* ws1 = (const float*)d_in[6];
    const float* bs1 = (const float*)d_in[7];
    const float* ws2 = (const float*)d_in[8];
    const float* bs2 = (const float*)d_in[9];
    float* out = (float*)d_out;

    void *pxh, *pw1h, *pw2h, *pws1h, *pws2h, *phb, *phsb;
    cudaGetSymbolAddress(&pxh,   g_xh);
    cudaGetSymbolAddress(&pw1h,  g_w1h);
    cudaGetSymbolAddress(&pw2h,  g_w2h);
    cudaGetSymbolAddress(&pws1h, g_ws1h);
    cudaGetSymbolAddress(&pws2h, g_ws2h);
    cudaGetSymbolAddress(&phb,   g_hb);
    cudaGetSymbolAddress(&phsb,  g_hsb);

    cudaFuncSetAttribute(mma_kernel<1, DIM, FDIM>,
                         cudaFuncAttributeMaxDynamicSharedMemorySize, SMEM_DYN);
    cudaFuncSetAttribute(mma_kernel<2, FDIM, DIM>,
                         cudaFuncAttributeMaxDynamicSharedMemorySize, SMEM_DYN);

    zero_kernel<<<1, 32>>>();
    gate_kernel<<<(NTOK * 32 + 255) / 256, 256>>>(x, gw);
    offsets_kernel<<<1, 1>>>();
    scatter_kernel<<<(NSLOT + 255) / 256, 256>>>();

    {
        long long t;
        t = (long long)NTOK * DIM;
        conv_h_kernel<<<(unsigned)((t / 4 + 255) / 256), 256>>>(x,   (__half*)pxh,   t);
        t = (long long)NEXP * FDIM * DIM;
        conv_h_kernel<<<(unsigned)((t / 4 + 255) / 256), 256>>>(w1,  (__half*)pw1h,  t);
        t = (long long)NEXP * DIM * FDIM;
        conv_h_kernel<<<(unsigned)((t / 4 + 255) / 256), 256>>>(w2,  (__half*)pw2h,  t);
        t = (long long)FDIM * DIM;
        conv_h_kernel<<<(unsigned)((t / 4 + 255) / 256), 256>>>(ws1, (__half*)pws1h, t);
        t = (long long)DIM * FDIM;
        conv_h_kernel<<<(unsigned)((t / 4 + 255) / 256), 256>>>(ws2, (__half*)pws2h, t);
    }

    // fc1: z = 0..7 routed experts, z = 8 shared expert
    mma_kernel<1, DIM, FDIM>
        <<<dim3(FDIM / BN, NSLOT / BM, NEXP + 1), MMA_THREADS, SMEM_DYN>>>(
            (const __half*)pxh, (const __half*)pxh,
            (const __half*)pw1h, (const __half*)pws1h, b1, bs1, nullptr);
    // fc2
    mma_kernel<2, FDIM, DIM>
        <<<dim3(DIM / BN, NSLOT / BM, NEXP + 1), MMA_THREADS, SMEM_DYN>>>(
            (const __half*)phb, (const __half*)phsb,
            (const __half*)pw2h, (const __half*)pws2h, b2, bs2, out);

    combine_kernel<<<(unsigned)(((long long)NTOK * DIM / 4 + 255) / 256), 256>>>(out);
}

// round 7
// speedup vs baseline: 6.8931x; 1.0058x over previous
#include <cuda_runtime.h>
#include <cuda_fp16.h>
#include <math.h>
#include <stdint.h>

#define NTOK 8192
#define DIM  768
#define FDIM 3072
#define NEXP 8
#define NSLOT (2*NTOK)

#define BM 128
#define BN 128
#define BK 32
#define SKB 80            // smem row stride bytes (32 fp16 + 8 pad)
#define OPBUF 10240       // 128*80 per operand
#define STGBUF 20480      // A+B per stage
#define NSTAGE 4
#define SMEM_DYN (NSTAGE*STGBUF)
#define MMA_THREADS 256

// ---------------- device-global scratch ----------------
__device__ int   g_counts[NEXP];
__device__ int   g_counts2[NEXP];
__device__ int   g_offsets[NEXP + 1];
__device__ int   g_te[NSLOT];
__device__ float g_tw[NSLOT];
__device__ int   g_perm[NSLOT];
__device__ float g_permw[NSLOT];
__device__ int   g_slotmap[NSLOT];

__device__ __align__(256) __half g_xh[(size_t)NTOK * DIM];
__device__ __align__(256) __half g_w1h[(size_t)NEXP * FDIM * DIM];
__device__ __align__(256) __half g_w2h[(size_t)NEXP * DIM * FDIM];
__device__ __align__(256) __half g_ws1h[(size_t)FDIM * DIM];
__device__ __align__(256) __half g_ws2h[(size_t)DIM * FDIM];
__device__ __align__(256) __half g_hb[(size_t)NSLOT * FDIM];
__device__ __align__(256) __half g_hsb[(size_t)NTOK * FDIM];
__device__ __align__(256) float  g_y[(size_t)NSLOT * DIM];

// ---------------- helpers ----------------
__device__ __forceinline__ uint32_t s2u(const void* p) {
    uint32_t a;
    asm("{ .reg .u64 t; cvta.to.shared.u64 t, %1; cvt.u32.u64 %0, t; }"
        : "=r"(a) : "l"(p));
    return a;
}

__device__ __forceinline__ void cp16(uint32_t dst, const void* src, bool pred) {
    int sz = pred ? 16 : 0;
    asm volatile("cp.async.cg.shared.global [%0], [%1], 16, %2;"
                 :: "r"(dst), "l"(src), "r"(sz) : "memory");
}
__device__ __forceinline__ void cp_commit() {
    asm volatile("cp.async.commit_group;" ::: "memory");
}
template <int N>
__device__ __forceinline__ void cp_wait() {
    asm volatile("cp.async.wait_group %0;" :: "n"(N) : "memory");
}

__device__ __forceinline__ void ldsm4(uint32_t (&r)[4], uint32_t addr) {
    asm volatile("ldmatrix.sync.aligned.m8n8.x4.shared.b16 {%0,%1,%2,%3}, [%4];"
                 : "=r"(r[0]), "=r"(r[1]), "=r"(r[2]), "=r"(r[3]) : "r"(addr));
}

__device__ __forceinline__ void mma16816(float (&c)[4], const uint32_t (&a)[4],
                                         uint32_t b0, uint32_t b1) {
    asm volatile(
        "mma.sync.aligned.m16n8k16.row.col.f32.f16.f16.f32 "
        "{%0,%1,%2,%3}, {%4,%5,%6,%7}, {%8,%9}, {%0,%1,%2,%3};"
        : "+f"(c[0]), "+f"(c[1]), "+f"(c[2]), "+f"(c[3])
        : "r"(a[0]), "r"(a[1]), "r"(a[2]), "r"(a[3]), "r"(b0), "r"(b1));
}

__device__ __forceinline__ float gelu_f(float v) {
    return 0.5f * v * (1.f + erff(v * 0.70710678118654752f));
}

// ---------------- small kernels ----------------
__global__ void zero_kernel() {
    int t = threadIdx.x;
    if (t < NEXP) { g_counts[t] = 0; g_counts2[t] = 0; }
}

// one warp per token: logits, top-2, renorm weights; ALSO emits fp16 x row.
__global__ void gate_kernel(const float* __restrict__ x,
                            const float* __restrict__ gw) {
    int gid  = blockIdx.x * blockDim.x + threadIdx.x;
    int tok  = gid >> 5;
    int lane = gid & 31;
    if (tok >= NTOK) return;

    const float* xr = x + (size_t)tok * DIM;
    float xv[24];
#pragma unroll
    for (int i = 0; i < 24; i++) xv[i] = xr[lane + 32 * i];

    // fused fp16 conversion of x (row already in registers)
    __half* xo = g_xh + (size_t)tok * DIM;
#pragma unroll
    for (int i = 0; i < 24; i++) xo[lane + 32 * i] = __float2half_rn(xv[i]);

    float logit[NEXP];
#pragma unroll
    for (int e = 0; e < NEXP; e++) {
        const float* w = gw + e * DIM;
        float s = 0.f;
#pragma unroll
        for (int i = 0; i < 24; i++) s = fmaf(xv[i], w[lane + 32 * i], s);
#pragma unroll
        for (int o = 16; o > 0; o >>= 1) s += __shfl_down_sync(0xffffffffu, s, o);
        logit[e] = s;
    }
    if (lane == 0) {
        int i1 = 0;
#pragma unroll
        for (int e = 1; e < NEXP; e++) if (logit[e] > logit[i1]) i1 = e;
        int i2 = (i1 == 0) ? 1 : 0;
#pragma unroll
        for (int e = 0; e < NEXP; e++) {
            if (e == i1 || e == i2) continue;
            if (logit[e] > logit[i2]) i2 = e;
        }
        float e2    = expf(logit[i2] - logit[i1]);
        float denom = 1.f + e2;
        g_te[2 * tok]     = i1;
        g_te[2 * tok + 1] = i2;
        g_tw[2 * tok]     = 1.f / denom;
        g_tw[2 * tok + 1] = e2 / denom;
        atomicAdd(&g_counts[i1], 1);
        atomicAdd(&g_counts[i2], 1);
    }
}

__global__ void offsets_kernel() {
    int s = 0;
    g_offsets[0] = 0;
#pragma unroll
    for (int e = 0; e < NEXP; e++) { s += g_counts[e]; g_offsets[e + 1] = s; }
}

__global__ void scatter_kernel() {
    int t = blockIdx.x * blockDim.x + threadIdx.x;
    if (t >= NSLOT) return;
    int e   = g_te[t];
    int pos = g_offsets[e] + atomicAdd(&g_counts2[e], 1);
    g_perm[pos]  = t >> 1;
    g_permw[pos] = g_tw[t];
    g_slotmap[t] = pos;
}

// one fused fp32->fp16 conversion over all four weight tensors
#define W1_Q  ((long long)NEXP * FDIM * DIM / 4)       // quads
#define W2_Q  ((long long)NEXP * DIM * FDIM / 4)
#define WS1_Q ((long long)FDIM * DIM / 4)
#define WS2_Q ((long long)DIM * FDIM / 4)
#define CONV_TOTAL_Q (W1_Q + W2_Q + WS1_Q + WS2_Q)

__global__ void conv_all_kernel(const float* __restrict__ w1,
                                const float* __restrict__ w2,
                                const float* __restrict__ ws1,
                                const float* __restrict__ ws2) {
    long long q = (long long)blockIdx.x * blockDim.x + threadIdx.x;
    if (q >= CONV_TOTAL_Q) return;
    const float* src;
    __half* dst;
    long long base;
    if (q < W1_Q)                      { src = w1;  dst = g_w1h;  base = q; }
    else if (q < W1_Q + W2_Q)          { src = w2;  dst = g_w2h;  base = q - W1_Q; }
    else if (q < W1_Q + W2_Q + WS1_Q)  { src = ws1; dst = g_ws1h; base = q - W1_Q - W2_Q; }
    else                               { src = ws2; dst = g_ws2h; base = q - W1_Q - W2_Q - WS1_Q; }
    long long i4 = base * 4;
    float4 v = *reinterpret_cast<const float4*>(src + i4);
    __half2 a, b;
    a.x = __float2half_rn(v.x); a.y = __float2half_rn(v.y);
    b.x = __float2half_rn(v.z); b.y = __float2half_rn(v.w);
    *reinterpret_cast<__half2*>(dst + i4)     = a;
    *reinterpret_cast<__half2*>(dst + i4 + 2) = b;
}

// ---------------- mma.sync GEMM (merged routed+shared) ----------------
// PHASE 1: fc1.  A = g_xh (routed: gathered via g_perm; z==8: direct)
//                B = w1h / ws1h  -> gelu -> fp16 hidden
// PHASE 2: fc2.  A = g_hb / g_hsb, B = w2h / ws2h
//                z==8 -> outp (store), z<8 -> g_y (weighted store)
template <int PHASE, int KD, int ND>
__global__ __launch_bounds__(MMA_THREADS, 2)
void mma_kernel(const __half* __restrict__ Ar, const __half* __restrict__ Ash,
                const __half* __restrict__ Br, const __half* __restrict__ Bsh,
                const float* __restrict__ biasR, const float* __restrict__ biasS,
                float* __restrict__ outp) {
    const int e = blockIdx.z;              // 0..7 routed, 8 = shared expert
    const bool se = (e == NEXP);
    int seg_start = 0, seg_len = NTOK;
    if (!se) {
        seg_start = g_offsets[e];
        seg_len   = g_offsets[e + 1] - seg_start;
    }
    const int m0 = blockIdx.y * BM;
    if (m0 >= seg_len) return;
    const int n0 = blockIdx.x * BN;

    extern __shared__ __align__(128) char smem[];
    const uint32_t sbase = s2u(smem);

    const int tid  = threadIdx.x;
    const int wid  = tid >> 5;
    const int lane = tid & 31;
    const int wm   = wid >> 2;
    const int wn   = wid & 3;

    // gmem pointers for cp.async
    const int lr = tid >> 2;     // 0..63
    const int cc = tid & 3;      // 8-halfword chunk
    const __half* aptr[2];
    bool av[2];
#pragma unroll
    for (int h = 0; h < 2; h++) {
        int gr = m0 + lr + h * 64;
        bool v = (gr < seg_len);
        const __half* p;
        if (se) {
            p = Ash + (size_t)(v ? gr : 0) * KD;
        } else if (PHASE == 1) {
            int tok = v ? g_perm[seg_start + gr] : 0;
            p = Ar + (size_t)tok * KD;
        } else {
            p = Ar + (size_t)(seg_start + (v ? gr : 0)) * KD;
        }
        aptr[h] = p + cc * 8;
        av[h]   = v;
    }
    const __half* bptr[2];
#pragma unroll
    for (int h = 0; h < 2; h++) {
        int brow = n0 + lr + h * 64;
        bptr[h] = (se ? Bsh + (size_t)brow * KD
                      : Br + ((size_t)e * ND + brow) * KD) + cc * 8;
    }

    const uint32_t sdst = (uint32_t)(lr * SKB + cc * 16);

    auto load_tile = [&](int kt, int buf) {
        const int k0 = kt * BK;
        uint32_t da = sbase + buf * STGBUF + sdst;
        uint32_t db = da + OPBUF;
        cp16(da,            aptr[0] + k0, av[0]);
        cp16(da + 64 * SKB, aptr[1] + k0, av[1]);
        cp16(db,            bptr[0] + k0, true);
        cp16(db + 64 * SKB, bptr[1] + k0, true);
    };

    const uint32_t aoff = (uint32_t)((wm * 64 + (lane & 15)) * SKB + (lane >> 4) * 16);
    const uint32_t boff = (uint32_t)((wn * 32 + (lane & 15)) * SKB + (lane >> 4) * 16)
                          + OPBUF;

    float acc[4][4][4];
#pragma unroll
    for (int i = 0; i < 4; i++)
#pragma unroll
        for (int j = 0; j < 4; j++)
#pragma unroll
            for (int q = 0; q < 4; q++) acc[i][j][q] = 0.f;

    const int nt = KD / BK;
    load_tile(0, 0); cp_commit();
    load_tile(1, 1); cp_commit();
    load_tile(2, 2); cp_commit();

    int buf = 0;
    for (int t = 0; t < nt; t++) {
        cp_wait<2>();
        __syncthreads();

        const uint32_t ab = sbase + buf * STGBUF + aoff;
        const uint32_t bb = sbase + buf * STGBUF + boff;
#pragma unroll
        for (int ks = 0; ks < 2; ks++) {
            uint32_t br[2][4];
            ldsm4(br[0], bb + ks * 32);
            ldsm4(br[1], bb + 1280 + ks * 32);
#pragma unroll
            for (int i = 0; i < 4; i++) {
                uint32_t ar[4];
                ldsm4(ar, ab + i * 1280 + ks * 32);
#pragma unroll
                for (int jn = 0; jn < 4; jn++) {
                    int jp = jn >> 1, sub = jn & 1;
                    mma16816(acc[i][jn], ar, br[jp][sub], br[jp][sub + 2]);
                }
            }
        }
        if (t + 3 < nt) load_tile(t + 3, (t + 3) % NSTAGE);
        cp_commit();
        buf = (buf + 1 == NSTAGE) ? 0 : buf + 1;
    }

    // ---- epilogue ----
    const float* bias = se ? biasS : biasR + (size_t)e * ND;
    const int colb = wn * 32 + (lane & 3) * 2;
#pragma unroll
    for (int i = 0; i < 4; i++) {
#pragma unroll
        for (int half = 0; half < 2; half++) {
            const int rl = wm * 64 + i * 16 + (lane >> 2) + half * 8;
            const int gr = m0 + rl;
            if (gr >= seg_len) continue;
            float wgt = 0.f;
            if (PHASE == 2 && !se) wgt = g_permw[seg_start + gr];
#pragma unroll
            for (int jn = 0; jn < 4; jn++) {
                const int c = n0 + colb + jn * 8;
                float v0 = acc[i][jn][2 * half]     + bias[c];
                float v1 = acc[i][jn][2 * half + 1] + bias[c + 1];
                if (PHASE == 1) {
                    v0 = gelu_f(v0); v1 = gelu_f(v1);
                    __half2 hp;
                    hp.x = __float2half_rn(v0);
                    hp.y = __float2half_rn(v1);
                    __half* hout = se ? g_hsb : g_hb;
                    size_t base = se ? (size_t)gr * FDIM
                                     : (size_t)(seg_start + gr) * FDIM;
                    *reinterpret_cast<__half2*>(hout + base + c) = hp;
                } else if (se) {
                    float2 o; o.x = v0; o.y = v1;
                    *reinterpret_cast<float2*>(outp + (size_t)gr * DIM + c) = o;
                } else {
                    float2 o; o.x = wgt * v0; o.y = wgt * v1;
                    *reinterpret_cast<float2*>(g_y + (size_t)(seg_start + gr) * DIM + c) = o;
                }
            }
        }
    }
}

// out[tok] += y[slot0] + y[slot1]
__global__ void combine_kernel(float* __restrict__ out) {
    long long i = (long long)blockIdx.x * blockDim.x + threadIdx.x;
    const long long total = (long long)NTOK * DIM / 4;
    if (i >= total) return;
    int tok = (int)(i / (DIM / 4));
    int cc  = (int)(i % (DIM / 4));
    int s0 = g_slotmap[2 * tok];
    int s1 = g_slotmap[2 * tok + 1];
    float4 b  = reinterpret_cast<float4*>(out)[i];
    float4 y0 = *(reinterpret_cast<const float4*>(g_y + (size_t)s0 * DIM) + cc);
    float4 y1 = *(reinterpret_cast<const float4*>(g_y + (size_t)s1 * DIM) + cc);
    b.x += y0.x + y1.x;
    b.y += y0.y + y1.y;
    b.z += y0.z + y1.z;
    b.w += y0.w + y1.w;
    reinterpret_cast<float4*>(out)[i] = b;
}

// ---------------- launch ----------------
extern "C" void kernel_launch(void* const* d_in, const int* in_sizes, int n_in,
                              void* d_out, int out_size) {
    const float* x   = (const float*)d_in[0];
    const float* gw  = (const float*)d_in[1];
    const float* w1  = (const float*)d_in[2];
    const float* b1  = (const float*)d_in[3];
    const float* w2  = (const float*)d_in[4];
    const float* b2  = (const float*)d_in[5];
    const float* ws1 = (const float*)d_in[6];
    const float* bs1 = (const float*)d_in[7];
    const float* ws2 = (const float*)d_in[8];
    const float* bs2 = (const float*)d_in[9];
    float* out = (float*)d_out;

    void *pxh, *pw1h, *pw2h, *pws1h, *pws2h, *phb, *phsb;
    cudaGetSymbolAddress(&pxh,   g_xh);
    cudaGetSymbolAddress(&pw1h,  g_w1h);
    cudaGetSymbolAddress(&pw2h,  g_w2h);
    cudaGetSymbolAddress(&pws1h, g_ws1h);
    cudaGetSymbolAddress(&pws2h, g_ws2h);
    cudaGetSymbolAddress(&phb,   g_hb);
    cudaGetSymbolAddress(&phsb,  g_hsb);

    cudaFuncSetAttribute(mma_kernel<1, DIM, FDIM>,
                         cudaFuncAttributeMaxDynamicSharedMemorySize, SMEM_DYN);
    cudaFuncSetAttribute(mma_kernel<2, FDIM, DIM>,
                         cudaFuncAttributeMaxDynamicSharedMemorySize, SMEM_DYN);

    // launch order chosen so ncu (-s 5 -c 1) profiles fc1 (launch #6)
    zero_kernel<<<1, 32>>>();                                              // 1
    gate_kernel<<<(NTOK * 32 + 255) / 256, 256>>>(x, gw);                  // 2
    offsets_kernel<<<1, 1>>>();                                            // 3
    scatter_kernel<<<(NSLOT + 255) / 256, 256>>>();                        // 4
    conv_all_kernel<<<(unsigned)((CONV_TOTAL_Q + 255) / 256), 256>>>(      // 5
        w1, w2, ws1, ws2);

    // fc1: z = 0..7 routed experts, z = 8 shared expert                   // 6
    mma_kernel<1, DIM, FDIM>
        <<<dim3(FDIM / BN, NSLOT / BM, NEXP + 1), MMA_THREADS, SMEM_DYN>>>(
            (const __half*)pxh, (const __half*)pxh,
            (const __half*)pw1h, (const __half*)pws1h, b1, bs1, nullptr);
    // fc2                                                                  // 7
    mma_kernel<2, FDIM, DIM>
        <<<dim3(DIM / BN, NSLOT / BM, NEXP + 1), MMA_THREADS, SMEM_DYN>>>(
            (const __half*)phb, (const __half*)phsb,
            (const __half*)pw2h, (const __half*)pws2h, b2, bs2, out);

    combine_kernel<<<(unsigned)(((long long)NTOK * DIM / 4 + 255) / 256), 256>>>(out); // 8
}